// round 1
// baseline (speedup 1.0000x reference)
#include <cuda_runtime.h>
#include <cuda_bf16.h>

#define B_ROWS 8192
#define H_DIM  1024
#define L_DIM  1024

#define BM 128
#define BN 128
#define BK 16
#define AS_STRIDE 132          // 128 + 4 padding to break bank conflicts on transposed stores
#define MAX_MTILES 80          // ceil(8192/128)+5 = 69 worst case; padded

// ---- device scratch (no allocations allowed) ----
__device__ int g_counts[8];
__device__ int g_offsets[8];
__device__ int g_cursor[8];
__device__ int g_perm[B_ROWS];
__device__ int g_tileGroup[MAX_MTILES];
__device__ int g_tileBase[MAX_MTILES];
__device__ int g_tileCnt[MAX_MTILES];

__global__ void k_reset() {
    if (threadIdx.x < 8) g_counts[threadIdx.x] = 0;
}

__global__ void k_count(const int* __restrict__ group) {
    int i = blockIdx.x * blockDim.x + threadIdx.x;
    if (i < B_ROWS) {
        int g = group[i];
        g = g < 0 ? 0 : (g > 5 ? 5 : g);
        atomicAdd(&g_counts[g], 1);
    }
}

__global__ void k_plan() {
    int off = 0;
    for (int g = 0; g < 6; g++) {
        g_offsets[g] = off;
        g_cursor[g]  = off;
        off += g_counts[g];
    }
    int t = 0;
    for (int g = 0; g < 5; g++) {
        int c = g_counts[g], o = g_offsets[g];
        for (int s = 0; s < c; s += BM) {
            g_tileGroup[t] = g;
            g_tileBase[t]  = o + s;
            g_tileCnt[t]   = (c - s) < BM ? (c - s) : BM;
            t++;
        }
    }
    for (; t < MAX_MTILES; t++) g_tileGroup[t] = -1;
}

__global__ void k_scatter(const int* __restrict__ group) {
    int i = blockIdx.x * blockDim.x + threadIdx.x;
    if (i < B_ROWS) {
        int g = group[i];
        g = g < 0 ? 0 : (g > 5 ? 5 : g);
        int pos = atomicAdd(&g_cursor[g], 1);
        g_perm[pos] = i;
    }
}

// group==5 rows: fill row with broadcast label value
__global__ void k_fill5(const int* __restrict__ group,
                        const int* __restrict__ labels,
                        float* __restrict__ out) {
    int row = blockIdx.x;
    if (group[row] != 5) return;
    float v = (float)labels[row];
    float4 vv = make_float4(v, v, v, v);
    float4* o = reinterpret_cast<float4*>(out + (size_t)row * L_DIM);
    o[threadIdx.x] = vv;   // 256 threads * 4 floats = 1024
}

// Tiled fp32 GEMM over gathered rows of one group per M-tile.
// out[perm_row, n] = sum_h hidden[perm_row, h] * W[g, n, h] + b[g, n]
__global__ __launch_bounds__(256, 2)
void k_gemm(const float* __restrict__ hidden,
            const float* __restrict__ W,
            const float* __restrict__ bias,
            float* __restrict__ out) {
    int t = blockIdx.y;
    int g = g_tileGroup[t];
    if (g < 0) return;
    int base = g_tileBase[t];
    int cnt  = g_tileCnt[t];
    int nBase = blockIdx.x * BN;

    const float* Wg = W + (size_t)g * L_DIM * H_DIM;

    __shared__ __align__(16) float As[BK][AS_STRIDE];
    __shared__ __align__(16) float Ws[BK][AS_STRIDE];
    __shared__ int srow[BM];

    int tid = threadIdx.x;
    if (tid < BM) srow[tid] = (tid < cnt) ? g_perm[base + tid] : -1;
    __syncthreads();

    // loader assignment: 512 float4 chunks for each operand tile, 2 per thread
    int f0 = tid, f1 = tid + 256;
    int am0 = f0 >> 2, ak0 = (f0 & 3) * 4;
    int am1 = f1 >> 2, ak1 = (f1 & 3) * 4;
    int arow0 = srow[am0];
    int arow1 = srow[am1];
    const float* aP0 = (arow0 >= 0) ? hidden + (size_t)arow0 * H_DIM + ak0 : nullptr;
    const float* aP1 = (arow1 >= 0) ? hidden + (size_t)arow1 * H_DIM + ak1 : nullptr;
    const float* wP0 = Wg + (size_t)(nBase + am0) * H_DIM + ak0;
    const float* wP1 = Wg + (size_t)(nBase + am1) * H_DIM + ak1;

    int tx = tid & 15, ty = tid >> 4;
    int m0 = ty * 8, n0 = tx * 8;

    float acc[8][8];
    #pragma unroll
    for (int i = 0; i < 8; i++)
        #pragma unroll
        for (int j = 0; j < 8; j++) acc[i][j] = 0.0f;

    const float4 z4 = make_float4(0.f, 0.f, 0.f, 0.f);

    for (int k0 = 0; k0 < H_DIM; k0 += BK) {
        float4 a0 = aP0 ? *reinterpret_cast<const float4*>(aP0 + k0) : z4;
        float4 a1 = aP1 ? *reinterpret_cast<const float4*>(aP1 + k0) : z4;
        float4 w0 = *reinterpret_cast<const float4*>(wP0 + k0);
        float4 w1 = *reinterpret_cast<const float4*>(wP1 + k0);

        __syncthreads();   // previous iteration's compute done before overwrite
        As[ak0 + 0][am0] = a0.x; As[ak0 + 1][am0] = a0.y;
        As[ak0 + 2][am0] = a0.z; As[ak0 + 3][am0] = a0.w;
        As[ak1 + 0][am1] = a1.x; As[ak1 + 1][am1] = a1.y;
        As[ak1 + 2][am1] = a1.z; As[ak1 + 3][am1] = a1.w;
        Ws[ak0 + 0][am0] = w0.x; Ws[ak0 + 1][am0] = w0.y;
        Ws[ak0 + 2][am0] = w0.z; Ws[ak0 + 3][am0] = w0.w;
        Ws[ak1 + 0][am1] = w1.x; Ws[ak1 + 1][am1] = w1.y;
        Ws[ak1 + 2][am1] = w1.z; Ws[ak1 + 3][am1] = w1.w;
        __syncthreads();

        #pragma unroll
        for (int kk = 0; kk < BK; kk++) {
            float4 aA = *reinterpret_cast<const float4*>(&As[kk][m0]);
            float4 aB = *reinterpret_cast<const float4*>(&As[kk][m0 + 4]);
            float4 bA = *reinterpret_cast<const float4*>(&Ws[kk][n0]);
            float4 bB = *reinterpret_cast<const float4*>(&Ws[kk][n0 + 4]);
            float ar[8] = {aA.x, aA.y, aA.z, aA.w, aB.x, aB.y, aB.z, aB.w};
            float br[8] = {bA.x, bA.y, bA.z, bA.w, bB.x, bB.y, bB.z, bB.w};
            #pragma unroll
            for (int i = 0; i < 8; i++)
                #pragma unroll
                for (int j = 0; j < 8; j++)
                    acc[i][j] = fmaf(ar[i], br[j], acc[i][j]);
        }
    }

    // epilogue: add bias, scatter rows
    const float* brow = bias + g * L_DIM + nBase + n0;
    float4 b0 = *reinterpret_cast<const float4*>(brow);
    float4 b1 = *reinterpret_cast<const float4*>(brow + 4);
    #pragma unroll
    for (int i = 0; i < 8; i++) {
        int r = srow[m0 + i];
        if (r < 0) continue;
        float* orow = out + (size_t)r * L_DIM + nBase + n0;
        float4 o0 = make_float4(acc[i][0] + b0.x, acc[i][1] + b0.y,
                                acc[i][2] + b0.z, acc[i][3] + b0.w);
        float4 o1 = make_float4(acc[i][4] + b1.x, acc[i][5] + b1.y,
                                acc[i][6] + b1.z, acc[i][7] + b1.w);
        *reinterpret_cast<float4*>(orow)     = o0;
        *reinterpret_cast<float4*>(orow + 4) = o1;
    }
}

extern "C" void kernel_launch(void* const* d_in, const int* in_sizes, int n_in,
                              void* d_out, int out_size) {
    const float* hidden = (const float*)d_in[0];
    const float* W      = (const float*)d_in[1];
    const float* bias   = (const float*)d_in[2];
    const int*   group  = (const int*)d_in[3];
    const int*   labels = (const int*)d_in[4];
    float* out = (float*)d_out;

    k_reset<<<1, 32>>>();
    k_count<<<B_ROWS / 256, 256>>>(group);
    k_plan<<<1, 1>>>();
    k_scatter<<<B_ROWS / 256, 256>>>(group);
    k_fill5<<<B_ROWS, 256>>>(group, labels, out);
    dim3 grid(L_DIM / BN, MAX_MTILES);
    k_gemm<<<grid, 256>>>(hidden, W, bias, out);
}

// round 3
// speedup vs baseline: 2.5779x; 2.5779x over previous
#include <cuda_runtime.h>
#include <cuda_bf16.h>
#include <cstdint>

#define B_ROWS 8192
#define H_DIM  1024
#define L_DIM  1024
#define NHEADS 5

#define BM 128
#define BN 128
#define KS 32            // K elements per smem stage
#define NSEG 3
#define NC (NSEG * H_DIM / KS)   // 96 stages
#define MAX_MTILES 80
#define STAGE_BYTES 16384        // A 8KB + B 8KB
#define NSTAGE 3

// ---------------- device scratch (static, no allocations) ----------------
__device__ int g_counts[8];
__device__ int g_offsets[8];
__device__ int g_cursor[8];
__device__ int g_perm[B_ROWS];
__device__ int g_tileGroup[MAX_MTILES];
__device__ int g_tileBase[MAX_MTILES];
__device__ int g_tileCnt[MAX_MTILES];

__device__ __nv_bfloat16 g_hid_hi[B_ROWS * H_DIM];
__device__ __nv_bfloat16 g_hid_lo[B_ROWS * H_DIM];
__device__ __nv_bfloat16 g_W_hi[NHEADS * L_DIM * H_DIM];
__device__ __nv_bfloat16 g_W_lo[NHEADS * L_DIM * H_DIM];

// ---------------- helpers ----------------
__device__ __forceinline__ uint32_t smem_u32(const void* p) {
    uint32_t a;
    asm("{ .reg .u64 t; cvta.to.shared.u64 t, %1; cvt.u32.u64 %0, t; }" : "=r"(a) : "l"(p));
    return a;
}

#define LDSM_X4(r, addr) \
    asm volatile("ldmatrix.sync.aligned.m8n8.x4.shared.b16 {%0,%1,%2,%3}, [%4];" \
        : "=r"((r)[0]), "=r"((r)[1]), "=r"((r)[2]), "=r"((r)[3]) : "r"(addr))

#define CP_ASYNC16(dst, src, sz) \
    asm volatile("cp.async.cg.shared.global [%0], [%1], 16, %2;" \
        :: "r"(dst), "l"(src), "r"(sz) : "memory")
#define CP_COMMIT() asm volatile("cp.async.commit_group;" ::: "memory")
#define CP_WAIT2()  asm volatile("cp.async.wait_group 2;" ::: "memory")
#define CP_WAIT1()  asm volatile("cp.async.wait_group 1;" ::: "memory")
#define CP_WAIT0()  asm volatile("cp.async.wait_group 0;" ::: "memory")

__device__ __forceinline__ void mma16816(float* d, const uint32_t* a, uint32_t b0, uint32_t b1) {
    asm volatile(
        "mma.sync.aligned.m16n8k16.row.col.f32.bf16.bf16.f32 "
        "{%0,%1,%2,%3}, {%4,%5,%6,%7}, {%8,%9}, {%0,%1,%2,%3};"
        : "+f"(d[0]), "+f"(d[1]), "+f"(d[2]), "+f"(d[3])
        : "r"(a[0]), "r"(a[1]), "r"(a[2]), "r"(a[3]), "r"(b0), "r"(b1));
}

// swizzled byte offset within a 128-row x 64-byte tile
__device__ __forceinline__ uint32_t swz(int row, int chunk) {
    return (uint32_t)(row * 64 + ((chunk ^ ((row >> 1) & 3)) << 4));
}

// ---------------- small kernels ----------------
__global__ void k_reset() { if (threadIdx.x < 8) g_counts[threadIdx.x] = 0; }

__global__ void k_count(const int* __restrict__ group) {
    int i = blockIdx.x * blockDim.x + threadIdx.x;
    if (i < B_ROWS) {
        int g = group[i]; g = g < 0 ? 0 : (g > 5 ? 5 : g);
        atomicAdd(&g_counts[g], 1);
    }
}

__global__ void k_plan() {
    int off = 0;
    for (int g = 0; g < 6; g++) { g_offsets[g] = off; g_cursor[g] = off; off += g_counts[g]; }
    int t = 0;
    for (int g = 0; g < 5; g++) {
        int c = g_counts[g], o = g_offsets[g];
        for (int s = 0; s < c; s += BM) {
            g_tileGroup[t] = g; g_tileBase[t] = o + s;
            g_tileCnt[t] = (c - s) < BM ? (c - s) : BM; t++;
        }
    }
    for (; t < MAX_MTILES; t++) g_tileGroup[t] = -1;
}

__global__ void k_scatter(const int* __restrict__ group) {
    int i = blockIdx.x * blockDim.x + threadIdx.x;
    if (i < B_ROWS) {
        int g = group[i]; g = g < 0 ? 0 : (g > 5 ? 5 : g);
        int pos = atomicAdd(&g_cursor[g], 1);
        g_perm[pos] = i;
    }
}

__global__ void k_fill5(const int* __restrict__ group, const int* __restrict__ labels,
                        float* __restrict__ out) {
    int row = blockIdx.x;
    if (group[row] != 5) return;
    float v = (float)labels[row];
    float4 vv = make_float4(v, v, v, v);
    reinterpret_cast<float4*>(out + (size_t)row * L_DIM)[threadIdx.x] = vv;
}

__device__ __forceinline__ void split_bf16(float x, unsigned short& hi, unsigned short& lo) {
    __nv_bfloat16 h = __float2bfloat16(x);
    __nv_bfloat16 l = __float2bfloat16(x - __bfloat162float(h));
    hi = __bfloat16_as_ushort(h);
    lo = __bfloat16_as_ushort(l);
}

__global__ void k_cvt_hidden(const float* __restrict__ x) {
    int i = blockIdx.x * blockDim.x + threadIdx.x;
    float4 v = reinterpret_cast<const float4*>(x)[i];
    unsigned short h0,l0,h1,l1,h2,l2,h3,l3;
    split_bf16(v.x, h0, l0); split_bf16(v.y, h1, l1);
    split_bf16(v.z, h2, l2); split_bf16(v.w, h3, l3);
    uint2 hp = make_uint2((uint32_t)h0 | ((uint32_t)h1 << 16), (uint32_t)h2 | ((uint32_t)h3 << 16));
    uint2 lp = make_uint2((uint32_t)l0 | ((uint32_t)l1 << 16), (uint32_t)l2 | ((uint32_t)l3 << 16));
    reinterpret_cast<uint2*>(g_hid_hi)[i] = hp;
    reinterpret_cast<uint2*>(g_hid_lo)[i] = lp;
}

__global__ void k_cvt_w(const float* __restrict__ x) {
    int i = blockIdx.x * blockDim.x + threadIdx.x;
    float4 v = reinterpret_cast<const float4*>(x)[i];
    unsigned short h0,l0,h1,l1,h2,l2,h3,l3;
    split_bf16(v.x, h0, l0); split_bf16(v.y, h1, l1);
    split_bf16(v.z, h2, l2); split_bf16(v.w, h3, l3);
    uint2 hp = make_uint2((uint32_t)h0 | ((uint32_t)h1 << 16), (uint32_t)h2 | ((uint32_t)h3 << 16));
    uint2 lp = make_uint2((uint32_t)l0 | ((uint32_t)l1 << 16), (uint32_t)l2 | ((uint32_t)l3 << 16));
    reinterpret_cast<uint2*>(g_W_hi)[i] = hp;
    reinterpret_cast<uint2*>(g_W_lo)[i] = lp;
}

// ---------------- HMMA GEMM ----------------
// out[perm_row, n] = sum over 3 bf16 segments + bias
__global__ __launch_bounds__(256, 2)
void k_gemm_mma(const float* __restrict__ bias, float* __restrict__ out) {
    int t = blockIdx.y;
    int g = g_tileGroup[t];
    if (g < 0) return;
    int base = g_tileBase[t];
    int cnt  = g_tileCnt[t];
    int nBase = blockIdx.x * BN;

    __shared__ __align__(1024) char smem[NSTAGE * STAGE_BYTES];  // 48 KB
    uint32_t sb = smem_u32(smem);

    int tid = threadIdx.x;
    int lane = tid & 31, wid = tid >> 5;
    int warp_m = wid & 3;        // 0..3 -> M offset 32*warp_m
    int warp_n = wid >> 2;       // 0..1 -> N offset 64*warp_n

    // ---- loader metadata (2 A chunks + 2 B chunks per thread per stage) ----
    int lrowA0 = tid >> 2, lrowA1 = 64 + (tid >> 2);
    int lchk   = tid & 3;
    int growA0 = (lrowA0 < cnt) ? g_perm[base + lrowA0] : -1;
    int growA1 = (lrowA1 < cnt) ? g_perm[base + lrowA1] : -1;
    uint32_t dA0 = swz(lrowA0, lchk);
    uint32_t dA1 = swz(lrowA1, lchk);
    uint32_t dB0 = 8192 + dA0;   // B rows share same (row,chunk) pattern
    uint32_t dB1 = 8192 + dA1;
    size_t aoff0 = (size_t)(growA0 < 0 ? 0 : growA0) * H_DIM + lchk * 8;
    size_t aoff1 = (size_t)(growA1 < 0 ? 0 : growA1) * H_DIM + lchk * 8;
    uint32_t szA0 = growA0 >= 0 ? 16u : 0u;
    uint32_t szA1 = growA1 >= 0 ? 16u : 0u;
    size_t boff0 = (size_t)(g * L_DIM + nBase + lrowA0) * H_DIM + lchk * 8;
    size_t boff1 = (size_t)(g * L_DIM + nBase + lrowA1) * H_DIM + lchk * 8;

    float acc[2][8][4];
    #pragma unroll
    for (int i = 0; i < 2; i++)
        #pragma unroll
        for (int j = 0; j < 8; j++)
            #pragma unroll
            for (int k = 0; k < 4; k++) acc[i][j][k] = 0.0f;

    // ---- stage loader ----
    auto load_stage = [&](int c) {
        int buf = c % NSTAGE;
        int seg = c >> 5;                 // 0,1,2
        int kOff = (c & 31) * KS;         // element offset within 1024
        const __nv_bfloat16* As = (seg == 1) ? g_hid_lo : g_hid_hi;
        const __nv_bfloat16* Bs = (seg == 2) ? g_W_lo  : g_W_hi;
        uint32_t s0 = sb + buf * STAGE_BYTES;
        CP_ASYNC16(s0 + dA0, As + aoff0 + kOff, szA0);
        CP_ASYNC16(s0 + dA1, As + aoff1 + kOff, szA1);
        CP_ASYNC16(s0 + dB0, Bs + boff0 + kOff, 16u);
        CP_ASYNC16(s0 + dB1, Bs + boff1 + kOff, 16u);
    };

    load_stage(0); CP_COMMIT();
    load_stage(1); CP_COMMIT();

    #pragma unroll 1
    for (int c = 0; c < NC; c++) {
        if (c + 2 < NC) { load_stage(c + 2); CP_COMMIT(); CP_WAIT2(); }
        else if (c + 1 < NC) { CP_WAIT1(); }
        else { CP_WAIT0(); }
        __syncthreads();

        int buf = c % NSTAGE;
        uint32_t Ab = sb + buf * STAGE_BYTES;
        uint32_t Bb = Ab + 8192;

        #pragma unroll
        for (int s = 0; s < 2; s++) {
            uint32_t a[2][4], b[4][4];
            #pragma unroll
            for (int mt = 0; mt < 2; mt++) {
                int row = warp_m * 32 + mt * 16 + (lane & 15);
                int ch  = 2 * s + (lane >> 4);
                LDSM_X4(a[mt], Ab + swz(row, ch));
            }
            #pragma unroll
            for (int nb = 0; nb < 4; nb++) {
                int row = warp_n * 64 + nb * 16 + (lane & 15);
                int ch  = 2 * s + (lane >> 4);
                LDSM_X4(b[nb], Bb + swz(row, ch));
            }
            #pragma unroll
            for (int mt = 0; mt < 2; mt++)
                #pragma unroll
                for (int nt = 0; nt < 8; nt++) {
                    int nb = nt >> 1, hf = nt & 1;
                    mma16816(acc[mt][nt], a[mt], b[nb][hf], b[nb][hf + 2]);
                }
        }
        __syncthreads();
    }

    // ---- epilogue ----
    // thread covers rows: warp_m*32 + mt*16 + lane/4 + h*8, cols: warp_n*64 + nt*8 + (lane%4)*2
    int rl = lane >> 2;
    int cl = (lane & 3) * 2;
    int outrow[2][2];
    #pragma unroll
    for (int mt = 0; mt < 2; mt++)
        #pragma unroll
        for (int h = 0; h < 2; h++) {
            int r = warp_m * 32 + mt * 16 + rl + h * 8;
            outrow[mt][h] = (r < cnt) ? g_perm[base + r] : -1;
        }
    const float* bptr = bias + g * L_DIM + nBase + warp_n * 64 + cl;
    float2 bv[8];
    #pragma unroll
    for (int nt = 0; nt < 8; nt++)
        bv[nt] = *reinterpret_cast<const float2*>(bptr + nt * 8);

    #pragma unroll
    for (int mt = 0; mt < 2; mt++)
        #pragma unroll
        for (int h = 0; h < 2; h++) {
            int r = outrow[mt][h];
            if (r < 0) continue;
            float* orow = out + (size_t)r * L_DIM + nBase + warp_n * 64 + cl;
            #pragma unroll
            for (int nt = 0; nt < 8; nt++) {
                float2 o;
                o.x = acc[mt][nt][2 * h + 0] + bv[nt].x;
                o.y = acc[mt][nt][2 * h + 1] + bv[nt].y;
                *reinterpret_cast<float2*>(orow + nt * 8) = o;
            }
        }
}

// ---------------- launch ----------------
extern "C" void kernel_launch(void* const* d_in, const int* in_sizes, int n_in,
                              void* d_out, int out_size) {
    const float* hidden = (const float*)d_in[0];
    const float* W      = (const float*)d_in[1];
    const float* bias   = (const float*)d_in[2];
    const int*   group  = (const int*)d_in[3];
    const int*   labels = (const int*)d_in[4];
    float* out = (float*)d_out;

    k_cvt_hidden<<<(B_ROWS * H_DIM / 4) / 256, 256>>>(hidden);
    k_cvt_w<<<(NHEADS * L_DIM * H_DIM / 4) / 256, 256>>>(W);
    k_reset<<<1, 32>>>();
    k_count<<<B_ROWS / 256, 256>>>(group);
    k_plan<<<1, 1>>>();
    k_scatter<<<B_ROWS / 256, 256>>>(group);
    k_fill5<<<B_ROWS, 256>>>(group, labels, out);
    dim3 grid(L_DIM / BN, MAX_MTILES);
    k_gemm_mma<<<grid, 256>>>(bias, out);
}

// round 5
// speedup vs baseline: 3.8558x; 1.4957x over previous
#include <cuda_runtime.h>
#include <cuda_fp16.h>
#include <cstdint>

#define B_ROWS 8192
#define H_DIM  1024
#define L_DIM  1024
#define NHEADS 5

#define BM 128
#define BN 128
#define KS 32                    // K elements per stage chunk
#define NC (H_DIM / KS)          // 32 chunks (both fp16 segments done per chunk)
#define MAX_MTILES 80
#define STAGE_BYTES 24576        // A_hi 8K + A_lo 8K + B 8K
#define NSTAGE 2

// ---------------- device scratch (static, no allocations) ----------------
__device__ int g_perm[B_ROWS];
__device__ int g_tileGroup[MAX_MTILES];
__device__ int g_tileBase[MAX_MTILES];
__device__ int g_tileCnt[MAX_MTILES];

__device__ __half g_hid_hi[B_ROWS * H_DIM];
__device__ __half g_hid_lo[B_ROWS * H_DIM];
__device__ __half g_W_hi[NHEADS * L_DIM * H_DIM];

// ---------------- helpers ----------------
__device__ __forceinline__ uint32_t smem_u32(const void* p) {
    uint32_t a;
    asm("{ .reg .u64 t; cvta.to.shared.u64 t, %1; cvt.u32.u64 %0, t; }" : "=r"(a) : "l"(p));
    return a;
}

#define LDSM_X4(r, addr) \
    asm volatile("ldmatrix.sync.aligned.m8n8.x4.shared.b16 {%0,%1,%2,%3}, [%4];" \
        : "=r"((r)[0]), "=r"((r)[1]), "=r"((r)[2]), "=r"((r)[3]) : "r"(addr))

#define CP_ASYNC16(dst, src, sz) \
    asm volatile("cp.async.cg.shared.global [%0], [%1], 16, %2;" \
        :: "r"(dst), "l"(src), "r"(sz) : "memory")
#define CP_COMMIT() asm volatile("cp.async.commit_group;" ::: "memory")
#define CP_WAIT1()  asm volatile("cp.async.wait_group 1;" ::: "memory")
#define CP_WAIT0()  asm volatile("cp.async.wait_group 0;" ::: "memory")

__device__ __forceinline__ void mma16816(float* d, const uint32_t* a, uint32_t b0, uint32_t b1) {
    asm volatile(
        "mma.sync.aligned.m16n8k16.row.col.f32.f16.f16.f32 "
        "{%0,%1,%2,%3}, {%4,%5,%6,%7}, {%8,%9}, {%0,%1,%2,%3};"
        : "+f"(d[0]), "+f"(d[1]), "+f"(d[2]), "+f"(d[3])
        : "r"(a[0]), "r"(a[1]), "r"(a[2]), "r"(a[3]), "r"(b0), "r"(b1));
}

// swizzled byte offset within a 128-row x 64-byte tile
__device__ __forceinline__ uint32_t swz(int row, int chunk) {
    return (uint32_t)(row * 64 + ((chunk ^ ((row >> 1) & 3)) << 4));
}

__device__ __forceinline__ uint32_t pack2(__half a, __half b) {
    return (uint32_t)__half_as_ushort(a) | ((uint32_t)__half_as_ushort(b) << 16);
}

// ---------------- fused prep: count + plan + scatter (single block) ----------------
__global__ void k_prep(const int* __restrict__ group) {
    __shared__ int s_cnt[8], s_off[8];
    int tid = threadIdx.x;
    if (tid < 8) s_cnt[tid] = 0;
    __syncthreads();
    int g[8];
    #pragma unroll
    for (int i = 0; i < 8; i++) {
        int row = tid + 1024 * i;
        int gg = group[row]; gg = gg < 0 ? 0 : (gg > 5 ? 5 : gg);
        g[i] = gg;
        atomicAdd(&s_cnt[gg], 1);
    }
    __syncthreads();
    if (tid == 0) {
        int off = 0;
        for (int k = 0; k < 6; k++) { s_off[k] = off; off += s_cnt[k]; }
        int t = 0;
        for (int k = 0; k < 5; k++) {
            int c = s_cnt[k], o = s_off[k];
            for (int s = 0; s < c; s += BM) {
                g_tileGroup[t] = k; g_tileBase[t] = o + s;
                g_tileCnt[t] = (c - s) < BM ? (c - s) : BM; t++;
            }
        }
        for (; t < MAX_MTILES; t++) g_tileGroup[t] = -1;
        for (int k = 0; k < 6; k++) s_cnt[k] = s_off[k];   // reuse as cursors
    }
    __syncthreads();
    #pragma unroll
    for (int i = 0; i < 8; i++) {
        int row = tid + 1024 * i;
        int pos = atomicAdd(&s_cnt[g[i]], 1);
        g_perm[pos] = row;
    }
}

__global__ void k_fill5(const int* __restrict__ group, const int* __restrict__ labels,
                        float* __restrict__ out) {
    int row = blockIdx.x;
    if (group[row] != 5) return;
    float v = (float)labels[row];
    float4 vv = make_float4(v, v, v, v);
    reinterpret_cast<float4*>(out + (size_t)row * L_DIM)[threadIdx.x] = vv;
}

// ---------------- fp16 conversions ----------------
__device__ __forceinline__ void split_fp16(float x, __half& hi, __half& lo) {
    hi = __float2half_rn(x);
    lo = __float2half_rn(x - __half2float(hi));
}

__global__ void k_cvt_hidden(const float* __restrict__ x) {
    int i = blockIdx.x * blockDim.x + threadIdx.x;   // float4 index
    float4 v = reinterpret_cast<const float4*>(x)[i];
    __half h0, l0, h1, l1, h2, l2, h3, l3;
    split_fp16(v.x, h0, l0); split_fp16(v.y, h1, l1);
    split_fp16(v.z, h2, l2); split_fp16(v.w, h3, l3);
    uint2 hp = make_uint2(pack2(h0, h1), pack2(h2, h3));
    uint2 lp = make_uint2(pack2(l0, l1), pack2(l2, l3));
    reinterpret_cast<uint2*>(g_hid_hi)[i] = hp;
    reinterpret_cast<uint2*>(g_hid_lo)[i] = lp;
}

__global__ void k_cvt_w(const float* __restrict__ x) {
    int i = blockIdx.x * blockDim.x + threadIdx.x;   // float4 index
    float4 v = reinterpret_cast<const float4*>(x)[i];
    uint2 hp = make_uint2(pack2(__float2half_rn(v.x), __float2half_rn(v.y)),
                          pack2(__float2half_rn(v.z), __float2half_rn(v.w)));
    reinterpret_cast<uint2*>(g_W_hi)[i] = hp;
}

// ---------------- HMMA GEMM: (A_hi + A_lo) * B_hi, shared-B stages ----------------
__global__ __launch_bounds__(256, 2)
void k_gemm_mma(const float* __restrict__ bias, float* __restrict__ out) {
    int t = blockIdx.y;
    int g = g_tileGroup[t];
    if (g < 0) return;
    int base = g_tileBase[t];
    int cnt  = g_tileCnt[t];
    int nBase = blockIdx.x * BN;

    __shared__ __align__(1024) char smem[NSTAGE * STAGE_BYTES];  // 48 KB
    uint32_t sb = smem_u32(smem);

    int tid = threadIdx.x;
    int lane = tid & 31, wid = tid >> 5;
    int warp_m = wid & 3;        // M offset 32*warp_m
    int warp_n = wid >> 2;       // N offset 64*warp_n

    // loader metadata: 2 slots/thread per 8KB tile (128 rows x 4 chunks of 16B)
    int lrow0 = tid >> 2, lrow1 = 64 + (tid >> 2);
    int lchk  = tid & 3;
    int grow0 = (lrow0 < cnt) ? g_perm[base + lrow0] : -1;
    int grow1 = (lrow1 < cnt) ? g_perm[base + lrow1] : -1;
    uint32_t d0 = swz(lrow0, lchk);
    uint32_t d1 = swz(lrow1, lchk);
    size_t aoff0 = (size_t)(grow0 < 0 ? 0 : grow0) * H_DIM + lchk * 8;
    size_t aoff1 = (size_t)(grow1 < 0 ? 0 : grow1) * H_DIM + lchk * 8;
    uint32_t szA0 = grow0 >= 0 ? 16u : 0u;
    uint32_t szA1 = grow1 >= 0 ? 16u : 0u;
    size_t boff0 = (size_t)(g * L_DIM + nBase + lrow0) * H_DIM + lchk * 8;
    size_t boff1 = (size_t)(g * L_DIM + nBase + lrow1) * H_DIM + lchk * 8;

    float acc[2][8][4];
    #pragma unroll
    for (int i = 0; i < 2; i++)
        #pragma unroll
        for (int j = 0; j < 8; j++)
            #pragma unroll
            for (int k = 0; k < 4; k++) acc[i][j][k] = 0.0f;

    auto load_stage = [&](int c) {
        int buf = c & 1;
        int kOff = c * KS;
        uint32_t s0 = sb + buf * STAGE_BYTES;
        CP_ASYNC16(s0 + d0,         g_hid_hi + aoff0 + kOff, szA0);
        CP_ASYNC16(s0 + d1,         g_hid_hi + aoff1 + kOff, szA1);
        CP_ASYNC16(s0 + 8192 + d0,  g_hid_lo + aoff0 + kOff, szA0);
        CP_ASYNC16(s0 + 8192 + d1,  g_hid_lo + aoff1 + kOff, szA1);
        CP_ASYNC16(s0 + 16384 + d0, g_W_hi + boff0 + kOff, 16u);
        CP_ASYNC16(s0 + 16384 + d1, g_W_hi + boff1 + kOff, 16u);
    };

    load_stage(0); CP_COMMIT();

    #pragma unroll 1
    for (int c = 0; c < NC; c++) {
        if (c + 1 < NC) { load_stage(c + 1); CP_COMMIT(); CP_WAIT1(); }
        else { CP_WAIT0(); }
        __syncthreads();

        int buf = c & 1;
        uint32_t AbH = sb + buf * STAGE_BYTES;
        uint32_t AbL = AbH + 8192;
        uint32_t Bb  = AbH + 16384;

        #pragma unroll
        for (int s = 0; s < 2; s++) {
            int ch = 2 * s + (lane >> 4);
            uint32_t b[4][4];
            #pragma unroll
            for (int nb = 0; nb < 4; nb++) {
                int row = warp_n * 64 + nb * 16 + (lane & 15);
                LDSM_X4(b[nb], Bb + swz(row, ch));
            }
            uint32_t a[2][4];
            #pragma unroll
            for (int mt = 0; mt < 2; mt++) {
                int row = warp_m * 32 + mt * 16 + (lane & 15);
                LDSM_X4(a[mt], AbH + swz(row, ch));
            }
            #pragma unroll
            for (int mt = 0; mt < 2; mt++)
                #pragma unroll
                for (int nt = 0; nt < 8; nt++) {
                    int nb = nt >> 1, hf = nt & 1;
                    mma16816(acc[mt][nt], a[mt], b[nb][hf], b[nb][hf + 2]);
                }
            #pragma unroll
            for (int mt = 0; mt < 2; mt++) {
                int row = warp_m * 32 + mt * 16 + (lane & 15);
                LDSM_X4(a[mt], AbL + swz(row, ch));
            }
            #pragma unroll
            for (int mt = 0; mt < 2; mt++)
                #pragma unroll
                for (int nt = 0; nt < 8; nt++) {
                    int nb = nt >> 1, hf = nt & 1;
                    mma16816(acc[mt][nt], a[mt], b[nb][hf], b[nb][hf + 2]);
                }
        }
        __syncthreads();
    }

    // ---- epilogue ----
    int rl = lane >> 2;
    int cl = (lane & 3) * 2;
    int outrow[2][2];
    #pragma unroll
    for (int mt = 0; mt < 2; mt++)
        #pragma unroll
        for (int h = 0; h < 2; h++) {
            int r = warp_m * 32 + mt * 16 + rl + h * 8;
            outrow[mt][h] = (r < cnt) ? g_perm[base + r] : -1;
        }
    const float* bptr = bias + g * L_DIM + nBase + warp_n * 64 + cl;
    float2 bv[8];
    #pragma unroll
    for (int nt = 0; nt < 8; nt++)
        bv[nt] = *reinterpret_cast<const float2*>(bptr + nt * 8);

    #pragma unroll
    for (int mt = 0; mt < 2; mt++)
        #pragma unroll
        for (int h = 0; h < 2; h++) {
            int r = outrow[mt][h];
            if (r < 0) continue;
            float* orow = out + (size_t)r * L_DIM + nBase + warp_n * 64 + cl;
            #pragma unroll
            for (int nt = 0; nt < 8; nt++) {
                float2 o;
                o.x = acc[mt][nt][2 * h + 0] + bv[nt].x;
                o.y = acc[mt][nt][2 * h + 1] + bv[nt].y;
                *reinterpret_cast<float2*>(orow + nt * 8) = o;
            }
        }
}

// ---------------- launch ----------------
extern "C" void kernel_launch(void* const* d_in, const int* in_sizes, int n_in,
                              void* d_out, int out_size) {
    const float* hidden = (const float*)d_in[0];
    const float* W      = (const float*)d_in[1];
    const float* bias   = (const float*)d_in[2];
    const int*   group  = (const int*)d_in[3];
    const int*   labels = (const int*)d_in[4];
    float* out = (float*)d_out;

    k_cvt_w<<<(NHEADS * L_DIM * H_DIM / 4) / 256, 256>>>(W);
    k_cvt_hidden<<<(B_ROWS * H_DIM / 4) / 256, 256>>>(hidden);
    k_prep<<<1, 1024>>>(group);
    k_fill5<<<B_ROWS, 256>>>(group, labels, out);
    dim3 grid(L_DIM / BN, MAX_MTILES);
    k_gemm_mma<<<grid, 256>>>(bias, out);
}

// round 6
// speedup vs baseline: 5.7702x; 1.4965x over previous
#include <cuda_runtime.h>
#include <cuda_fp16.h>
#include <cstdint>

#define B_ROWS 8192
#define H_DIM  1024
#define L_DIM  1024
#define NHEADS 5

#define BM 128
#define BN 128
#define KS 32                    // K elements per stage
#define NC (H_DIM / KS)          // 32 stages
#define MAX_MTILES 80
#define STAGE_BYTES 16384        // A 8K + B 8K
#define NSTAGE 3

// ---------------- device scratch (static, no allocations) ----------------
__device__ int g_perm[B_ROWS];
__device__ int g_tileGroup[MAX_MTILES];
__device__ int g_tileBase[MAX_MTILES];
__device__ int g_tileCnt[MAX_MTILES];

__device__ __half g_hid[B_ROWS * H_DIM];
__device__ __half g_W[NHEADS * L_DIM * H_DIM];

// ---------------- helpers ----------------
__device__ __forceinline__ uint32_t smem_u32(const void* p) {
    uint32_t a;
    asm("{ .reg .u64 t; cvta.to.shared.u64 t, %1; cvt.u32.u64 %0, t; }" : "=r"(a) : "l"(p));
    return a;
}

#define LDSM_X4(r, addr) \
    asm volatile("ldmatrix.sync.aligned.m8n8.x4.shared.b16 {%0,%1,%2,%3}, [%4];" \
        : "=r"((r)[0]), "=r"((r)[1]), "=r"((r)[2]), "=r"((r)[3]) : "r"(addr))

#define CP_ASYNC16(dst, src, sz) \
    asm volatile("cp.async.cg.shared.global [%0], [%1], 16, %2;" \
        :: "r"(dst), "l"(src), "r"(sz) : "memory")
#define CP_COMMIT() asm volatile("cp.async.commit_group;" ::: "memory")
#define CP_WAIT2()  asm volatile("cp.async.wait_group 2;" ::: "memory")
#define CP_WAIT1()  asm volatile("cp.async.wait_group 1;" ::: "memory")
#define CP_WAIT0()  asm volatile("cp.async.wait_group 0;" ::: "memory")

__device__ __forceinline__ void mma16816(float* d, const uint32_t* a, uint32_t b0, uint32_t b1) {
    asm volatile(
        "mma.sync.aligned.m16n8k16.row.col.f32.f16.f16.f32 "
        "{%0,%1,%2,%3}, {%4,%5,%6,%7}, {%8,%9}, {%0,%1,%2,%3};"
        : "+f"(d[0]), "+f"(d[1]), "+f"(d[2]), "+f"(d[3])
        : "r"(a[0]), "r"(a[1]), "r"(a[2]), "r"(a[3]), "r"(b0), "r"(b1));
}

// swizzled byte offset within a 128-row x 64-byte tile
__device__ __forceinline__ uint32_t swz(int row, int chunk) {
    return (uint32_t)(row * 64 + ((chunk ^ ((row >> 1) & 3)) << 4));
}

__device__ __forceinline__ uint32_t pack2(__half a, __half b) {
    return (uint32_t)__half_as_ushort(a) | ((uint32_t)__half_as_ushort(b) << 16);
}

// ---------------- fused prep: count + plan + scatter (single block) ----------------
__global__ void k_prep(const int* __restrict__ group) {
    __shared__ int s_cnt[8], s_off[8];
    int tid = threadIdx.x;
    if (tid < 8) s_cnt[tid] = 0;
    __syncthreads();
    int g[8];
    #pragma unroll
    for (int i = 0; i < 8; i++) {
        int row = tid + 1024 * i;
        int gg = group[row]; gg = gg < 0 ? 0 : (gg > 5 ? 5 : gg);
        g[i] = gg;
        atomicAdd(&s_cnt[gg], 1);
    }
    __syncthreads();
    if (tid == 0) {
        int off = 0;
        for (int k = 0; k < 6; k++) { s_off[k] = off; off += s_cnt[k]; }
        int t = 0;
        for (int k = 0; k < 5; k++) {
            int c = s_cnt[k], o = s_off[k];
            for (int s = 0; s < c; s += BM) {
                g_tileGroup[t] = k; g_tileBase[t] = o + s;
                g_tileCnt[t] = (c - s) < BM ? (c - s) : BM; t++;
            }
        }
        for (; t < MAX_MTILES; t++) g_tileGroup[t] = -1;
        for (int k = 0; k < 6; k++) s_cnt[k] = s_off[k];   // reuse as cursors
    }
    __syncthreads();
    #pragma unroll
    for (int i = 0; i < 8; i++) {
        int row = tid + 1024 * i;
        int pos = atomicAdd(&s_cnt[g[i]], 1);
        g_perm[pos] = row;
    }
}

// group==5 rows: 256 blocks x 32 rows; 8 threads per row
__global__ void k_fill5(const int* __restrict__ group, const int* __restrict__ labels,
                        float* __restrict__ out) {
    int row = blockIdx.x * 32 + (threadIdx.x >> 3);
    if (group[row] != 5) return;
    float v = (float)labels[row];
    float4 vv = make_float4(v, v, v, v);
    float4* o = reinterpret_cast<float4*>(out + (size_t)row * L_DIM);
    int c = threadIdx.x & 7;
    #pragma unroll
    for (int i = 0; i < 32; i++) o[c + i * 8] = vv;
}

// ---------------- fp16 conversions ----------------
__global__ void k_cvt_hidden(const float* __restrict__ x) {
    int i = blockIdx.x * blockDim.x + threadIdx.x;   // float4 index
    float4 v = reinterpret_cast<const float4*>(x)[i];
    uint2 hp = make_uint2(pack2(__float2half_rn(v.x), __float2half_rn(v.y)),
                          pack2(__float2half_rn(v.z), __float2half_rn(v.w)));
    reinterpret_cast<uint2*>(g_hid)[i] = hp;
}

__global__ void k_cvt_w(const float* __restrict__ x) {
    int i = blockIdx.x * blockDim.x + threadIdx.x;   // float4 index
    float4 v = reinterpret_cast<const float4*>(x)[i];
    uint2 hp = make_uint2(pack2(__float2half_rn(v.x), __float2half_rn(v.y)),
                          pack2(__float2half_rn(v.z), __float2half_rn(v.w)));
    reinterpret_cast<uint2*>(g_W)[i] = hp;
}

// ---------------- HMMA GEMM, single fp16 term, 3-stage pipeline ----------------
__global__ __launch_bounds__(256, 2)
void k_gemm_mma(const float* __restrict__ bias, float* __restrict__ out) {
    int t = blockIdx.y;
    int g = g_tileGroup[t];
    if (g < 0) return;
    int base = g_tileBase[t];
    int cnt  = g_tileCnt[t];
    int nBase = blockIdx.x * BN;

    __shared__ __align__(1024) char smem[NSTAGE * STAGE_BYTES];  // 48 KB
    uint32_t sb = smem_u32(smem);

    int tid = threadIdx.x;
    int lane = tid & 31, wid = tid >> 5;
    int warp_m = wid & 3;        // M offset 32*warp_m
    int warp_n = wid >> 2;       // N offset 64*warp_n

    // loader metadata: 2 slots/thread per 8KB tile
    int lrow0 = tid >> 2, lrow1 = 64 + (tid >> 2);
    int lchk  = tid & 3;
    int grow0 = (lrow0 < cnt) ? g_perm[base + lrow0] : -1;
    int grow1 = (lrow1 < cnt) ? g_perm[base + lrow1] : -1;
    uint32_t d0 = swz(lrow0, lchk);
    uint32_t d1 = swz(lrow1, lchk);
    size_t aoff0 = (size_t)(grow0 < 0 ? 0 : grow0) * H_DIM + lchk * 8;
    size_t aoff1 = (size_t)(grow1 < 0 ? 0 : grow1) * H_DIM + lchk * 8;
    uint32_t szA0 = grow0 >= 0 ? 16u : 0u;
    uint32_t szA1 = grow1 >= 0 ? 16u : 0u;
    size_t boff0 = (size_t)(g * L_DIM + nBase + lrow0) * H_DIM + lchk * 8;
    size_t boff1 = (size_t)(g * L_DIM + nBase + lrow1) * H_DIM + lchk * 8;

    float acc[2][8][4];
    #pragma unroll
    for (int i = 0; i < 2; i++)
        #pragma unroll
        for (int j = 0; j < 8; j++)
            #pragma unroll
            for (int k = 0; k < 4; k++) acc[i][j][k] = 0.0f;

    auto load_stage = [&](int c) {
        int buf = c % NSTAGE;
        int kOff = c * KS;
        uint32_t s0 = sb + buf * STAGE_BYTES;
        CP_ASYNC16(s0 + d0,        g_hid + aoff0 + kOff, szA0);
        CP_ASYNC16(s0 + d1,        g_hid + aoff1 + kOff, szA1);
        CP_ASYNC16(s0 + 8192 + d0, g_W + boff0 + kOff, 16u);
        CP_ASYNC16(s0 + 8192 + d1, g_W + boff1 + kOff, 16u);
    };

    load_stage(0); CP_COMMIT();
    load_stage(1); CP_COMMIT();

    #pragma unroll 1
    for (int c = 0; c < NC; c++) {
        if (c + 2 < NC) { load_stage(c + 2); CP_COMMIT(); CP_WAIT2(); }
        else if (c + 1 < NC) { CP_WAIT1(); }
        else { CP_WAIT0(); }
        __syncthreads();

        int buf = c % NSTAGE;
        uint32_t Ab = sb + buf * STAGE_BYTES;
        uint32_t Bb = Ab + 8192;

        #pragma unroll
        for (int s = 0; s < 2; s++) {
            int ch = 2 * s + (lane >> 4);
            uint32_t b[4][4];
            #pragma unroll
            for (int nb = 0; nb < 4; nb++) {
                int row = warp_n * 64 + nb * 16 + (lane & 15);
                LDSM_X4(b[nb], Bb + swz(row, ch));
            }
            uint32_t a[2][4];
            #pragma unroll
            for (int mt = 0; mt < 2; mt++) {
                int row = warp_m * 32 + mt * 16 + (lane & 15);
                LDSM_X4(a[mt], Ab + swz(row, ch));
            }
            #pragma unroll
            for (int mt = 0; mt < 2; mt++)
                #pragma unroll
                for (int nt = 0; nt < 8; nt++) {
                    int nb = nt >> 1, hf = nt & 1;
                    mma16816(acc[mt][nt], a[mt], b[nb][hf], b[nb][hf + 2]);
                }
        }
        __syncthreads();
    }

    // ---- epilogue ----
    int rl = lane >> 2;
    int cl = (lane & 3) * 2;
    int outrow[2][2];
    #pragma unroll
    for (int mt = 0; mt < 2; mt++)
        #pragma unroll
        for (int h = 0; h < 2; h++) {
            int r = warp_m * 32 + mt * 16 + rl + h * 8;
            outrow[mt][h] = (r < cnt) ? g_perm[base + r] : -1;
        }
    const float* bptr = bias + g * L_DIM + nBase + warp_n * 64 + cl;
    float2 bv[8];
    #pragma unroll
    for (int nt = 0; nt < 8; nt++)
        bv[nt] = *reinterpret_cast<const float2*>(bptr + nt * 8);

    #pragma unroll
    for (int mt = 0; mt < 2; mt++)
        #pragma unroll
        for (int h = 0; h < 2; h++) {
            int r = outrow[mt][h];
            if (r < 0) continue;
            float* orow = out + (size_t)r * L_DIM + nBase + warp_n * 64 + cl;
            #pragma unroll
            for (int nt = 0; nt < 8; nt++) {
                float2 o;
                o.x = acc[mt][nt][2 * h + 0] + bv[nt].x;
                o.y = acc[mt][nt][2 * h + 1] + bv[nt].y;
                *reinterpret_cast<float2*>(orow + nt * 8) = o;
            }
        }
}

// ---------------- launch ----------------
extern "C" void kernel_launch(void* const* d_in, const int* in_sizes, int n_in,
                              void* d_out, int out_size) {
    const float* hidden = (const float*)d_in[0];
    const float* W      = (const float*)d_in[1];
    const float* bias   = (const float*)d_in[2];
    const int*   group  = (const int*)d_in[3];
    const int*   labels = (const int*)d_in[4];
    float* out = (float*)d_out;

    k_cvt_w<<<(NHEADS * L_DIM * H_DIM / 4) / 256, 256>>>(W);
    k_cvt_hidden<<<(B_ROWS * H_DIM / 4) / 256, 256>>>(hidden);
    k_prep<<<1, 1024>>>(group);
    k_fill5<<<B_ROWS / 32, 256>>>(group, labels, out);
    dim3 grid(L_DIM / BN, MAX_MTILES);
    k_gemm_mma<<<grid, 256>>>(bias, out);
}